// round 2
// baseline (speedup 1.0000x reference)
#include <cuda_runtime.h>

#define HID   256
#define TLEN  128
#define TPAD  144            // padded row: cols 128..143 are permanent zeros
#define INCH  1024
#define CTXD  16

typedef unsigned long long ull;

#define HSM_FLOATS   (256 * TPAD)      // 36864
#define WSU_FLOATS   (256 * 68)        // 17408 (weight stage / scratch union)
#define SMEM_FLOATS  (HSM_FLOATS + WSU_FLOATS + TLEN + 64)

__device__ __forceinline__ ull fma2(ull a, ull b, ull c) {
    ull d;
    asm("fma.rn.f32x2 %0, %1, %2, %3;" : "=l"(d) : "l"(a), "l"(b), "l"(c));
    return d;
}
__device__ __forceinline__ ull pk(float lo, float hi) {
    ull d;
    asm("mov.b64 %0, {%1, %2};" : "=l"(d) : "f"(lo), "f"(hi));
    return d;
}
__device__ __forceinline__ void upk(float& lo, float& hi, ull v) {
    asm("mov.b64 {%0, %1}, %2;" : "=f"(lo), "=f"(hi) : "l"(v));
}
__device__ __forceinline__ void load8(float r[8], const float* p) {
    float4 a = *(const float4*)(p);
    float4 b = *(const float4*)(p + 4);
    r[0]=a.x; r[1]=a.y; r[2]=a.z; r[3]=a.w;
    r[4]=b.x; r[5]=b.y; r[6]=b.z; r[7]=b.w;
}
__device__ __forceinline__ void store8(float* p, const float r[8]) {
    *(float4*)(p)     = make_float4(r[0], r[1], r[2], r[3]);
    *(float4*)(p + 4) = make_float4(r[4], r[5], r[6], r[7]);
}

// One dilated conv layer on f32x2 packed math.
// Thread (mg,ng) owns out rows [o0,o0+8) x cols [t0,t0+8) (4 packed pairs).
template<int D>
__device__ __forceinline__ void conv_layer(
    float* __restrict__ hsm, float* __restrict__ wsu, float* __restrict__ colfac,
    const float* __restrict__ cw, const float* __restrict__ cb,
    int tid, int mg, int ng, int t0, int o0)
{
    ull acc[8][4];
    #pragma unroll
    for (int m = 0; m < 8; m++)
        #pragma unroll
        for (int jj = 0; jj < 4; jj++) acc[m][jj] = 0ull;

    const int o = tid >> 1, half = tid & 1;

    for (int kc = 0; kc < 16; kc++) {
        __syncthreads();   // previous chunk's weight reads / scratch use done
        // stage duplicated weights: wsu[o][68] rows hold {wx,wx,wy,wy} per input chan
        {
            const float4* src = (const float4*)(cw + o * (HID * 2) + kc * 32 + half * 16);
            float4 s0 = src[0], s1 = src[1], s2 = src[2], s3 = src[3];
            float f[16] = { s0.x,s0.y,s0.z,s0.w, s1.x,s1.y,s1.z,s1.w,
                            s2.x,s2.y,s2.z,s2.w, s3.x,s3.y,s3.z,s3.w };
            float* dst = wsu + o * 68 + half * 32;
            #pragma unroll
            for (int ii = 0; ii < 8; ii++)
                *(float4*)(dst + ii * 4) = make_float4(f[2*ii], f[2*ii], f[2*ii+1], f[2*ii+1]);
        }
        __syncthreads();

        #pragma unroll 2
        for (int i = 0; i < 16; i++) {
            const float* hrow = hsm + (kc * 16 + i) * TPAD;
            ull h1p[4], h2p[4];
            if constexpr (D == 1) {
                float4 a = *(const float4*)(hrow + t0);
                float4 b = *(const float4*)(hrow + t0 + 4);
                float r8 = hrow[t0 + 8];           // col 128 is zero-pad for ng=15
                h1p[0] = pk(a.x, a.y); h1p[1] = pk(a.z, a.w);
                h1p[2] = pk(b.x, b.y); h1p[3] = pk(b.z, b.w);
                h2p[0] = pk(a.y, a.z); h2p[1] = pk(a.w, b.x);
                h2p[2] = pk(b.y, b.z); h2p[3] = pk(b.w, r8);
            } else {
                ulonglong2 a = *(const ulonglong2*)(hrow + t0);
                ulonglong2 b = *(const ulonglong2*)(hrow + t0 + 4);
                h1p[0] = a.x; h1p[1] = a.y; h1p[2] = b.x; h1p[3] = b.y;
                if constexpr (D <= 16) {
                    if constexpr (D == 2) {
                        h2p[0] = *(const ull*)(hrow + t0 + 2);
                        h2p[1] = *(const ull*)(hrow + t0 + 4);
                        h2p[2] = *(const ull*)(hrow + t0 + 6);
                        h2p[3] = *(const ull*)(hrow + t0 + 8);
                    } else {   // D = 4, 8, 16: 16B-aligned, pad covers the tail
                        ulonglong2 c  = *(const ulonglong2*)(hrow + t0 + D);
                        ulonglong2 d2 = *(const ulonglong2*)(hrow + t0 + D + 4);
                        h2p[0] = c.x; h2p[1] = c.y; h2p[2] = d2.x; h2p[3] = d2.y;
                    }
                } else {       // D = 32, 64: group fully in-row (values may be pad zeros) or fully zero
                    if (t0 + D + 7 < TPAD) {
                        ulonglong2 c  = *(const ulonglong2*)(hrow + t0 + D);
                        ulonglong2 d2 = *(const ulonglong2*)(hrow + t0 + D + 4);
                        h2p[0] = c.x; h2p[1] = c.y; h2p[2] = d2.x; h2p[3] = d2.y;
                    } else {
                        h2p[0] = 0ull; h2p[1] = 0ull; h2p[2] = 0ull; h2p[3] = 0ull;
                    }
                }
            }
            const float* wr = wsu + o0 * 68 + i * 4;
            #pragma unroll
            for (int m = 0; m < 8; m++) {
                ull wx = *(const ull*)(wr + m * 68);
                ull wy = *(const ull*)(wr + m * 68 + 2);
                #pragma unroll
                for (int jj = 0; jj < 4; jj++) acc[m][jj] = fma2(wx, h1p[jj], acc[m][jj]);
                #pragma unroll
                for (int jj = 0; jj < 4; jj++) acc[m][jj] = fma2(wy, h2p[jj], acc[m][jj]);
            }
        }
    }
    __syncthreads();   // all weight reads done before wsu reused as scratch

    // epilogue: bias + leaky relu + skip + column sums of squares + unit-norm
    float accf[8][8];
    #pragma unroll
    for (int m = 0; m < 8; m++)
        #pragma unroll
        for (int jj = 0; jj < 4; jj++) upk(accf[m][2*jj], accf[m][2*jj+1], acc[m][jj]);

    float psum[8];
    #pragma unroll
    for (int j = 0; j < 8; j++) psum[j] = 0.f;
    #pragma unroll
    for (int m = 0; m < 8; m++) {
        float bb = cb[o0 + m];
        float sk[8];
        load8(sk, hsm + (o0 + m) * TPAD + t0);
        #pragma unroll
        for (int j = 0; j < 8; j++) {
            float y = accf[m][j] + bb;
            y = (y > 0.f) ? y : 0.2f * y;
            y += sk[j];
            accf[m][j] = y;
            psum[j] = fmaf(y, y, psum[j]);
        }
    }
    store8(wsu + mg * TLEN + t0, psum);     // scratch[32][128]
    __syncthreads();
    if (tid < TLEN) {
        float s = 0.f;
        #pragma unroll
        for (int g = 0; g < 32; g++) s += wsu[g * TLEN + tid];
        colfac[tid] = 1.0f / (sqrtf(s) + 1e-8f);
    }
    __syncthreads();
    float fac[8];
    load8(fac, colfac + t0);
    #pragma unroll
    for (int m = 0; m < 8; m++) {
        #pragma unroll
        for (int j = 0; j < 8; j++) accf[m][j] *= fac[j];
        store8(hsm + (o0 + m) * TPAD + t0, accf[m]);
    }
    __syncthreads();
}

__global__ __launch_bounds__(512, 1)
void Model_26147760898465_kernel(
    const float* __restrict__ x,
    const float* __restrict__ proj_w, const float* __restrict__ proj_b,
    const float* __restrict__ conv_w, const float* __restrict__ conv_b,
    const float* __restrict__ ev_w,  const float* __restrict__ ev_b,
    const float* __restrict__ sw_w,  const float* __restrict__ sw_b,
    float* __restrict__ out)
{
    extern __shared__ float sm[];
    float* hsm    = sm;
    float* wsu    = sm + HSM_FLOATS;
    float* colfac = wsu + WSU_FLOATS;
    float* redv   = colfac + TLEN;
    int*   redi   = (int*)(redv + 32);

    const int tid = threadIdx.x;
    const int b   = blockIdx.x;
    const int mg  = tid >> 4, ng = tid & 15;
    const int t0  = ng * 8,   o0 = mg * 8;

    // ---------------- 1x1 projection (f32x2): h = proj_w @ x[b] + proj_b ----------------
    {
        ull acc[8][4];
        #pragma unroll
        for (int m = 0; m < 8; m++)
            #pragma unroll
            for (int jj = 0; jj < 4; jj++) acc[m][jj] = 0ull;

        const float* xb  = x + (size_t)b * INCH * TLEN;
        float* xs  = wsu;            // [16][128]
        float* pws = wsu + 2048;     // [256][36] duplicated weight pairs
        const int o = tid >> 1, half = tid & 1;

        for (int kc = 0; kc < 64; kc++) {
            __syncthreads();
            ((float4*)xs)[tid] = ((const float4*)(xb + kc * 16 * TLEN))[tid];
            {
                const float4* src = (const float4*)(proj_w + o * INCH + kc * 16 + half * 8);
                float4 s0 = src[0], s1 = src[1];
                float f[8] = { s0.x,s0.y,s0.z,s0.w, s1.x,s1.y,s1.z,s1.w };
                float* dst = pws + o * 36 + half * 16;
                #pragma unroll
                for (int ii = 0; ii < 8; ii++)
                    *(float2*)(dst + ii * 2) = make_float2(f[ii], f[ii]);
            }
            __syncthreads();

            #pragma unroll 2
            for (int i = 0; i < 16; i++) {
                const float* xr = xs + i * TLEN;
                ulonglong2 a  = *(const ulonglong2*)(xr + t0);
                ulonglong2 bq = *(const ulonglong2*)(xr + t0 + 4);
                ull hp[4] = { a.x, a.y, bq.x, bq.y };
                const float* wr = pws + o0 * 36 + i * 2;
                #pragma unroll
                for (int m = 0; m < 8; m++) {
                    ull w = *(const ull*)(wr + m * 36);
                    #pragma unroll
                    for (int jj = 0; jj < 4; jj++) acc[m][jj] = fma2(w, hp[jj], acc[m][jj]);
                }
            }
        }
        __syncthreads();
        #pragma unroll
        for (int m = 0; m < 8; m++) {
            float r[8];
            #pragma unroll
            for (int jj = 0; jj < 4; jj++) upk(r[2*jj], r[2*jj+1], acc[m][jj]);
            float bb = proj_b[o0 + m];
            #pragma unroll
            for (int j = 0; j < 8; j++) r[j] += bb;
            store8(hsm + (o0 + m) * TPAD + t0, r);
        }
        // zero the pad columns (128..143) of every row — stays zero all layers
        {
            float z[8] = {0,0,0,0,0,0,0,0};
            int zr = tid >> 1;
            int zc = TLEN + (tid & 1) * 8;
            store8(hsm + zr * TPAD + zc, z);
        }
        __syncthreads();
    }

    // ---------------- dilated conv stack (DILATIONS = 1,2,4,8,16,32,64,1) ----------------
    conv_layer<1 >(hsm, wsu, colfac, conv_w + 0 * HID * HID * 2, conv_b + 0 * HID, tid, mg, ng, t0, o0);
    conv_layer<2 >(hsm, wsu, colfac, conv_w + 1 * HID * HID * 2, conv_b + 1 * HID, tid, mg, ng, t0, o0);
    conv_layer<4 >(hsm, wsu, colfac, conv_w + 2 * HID * HID * 2, conv_b + 2 * HID, tid, mg, ng, t0, o0);
    conv_layer<8 >(hsm, wsu, colfac, conv_w + 3 * HID * HID * 2, conv_b + 3 * HID, tid, mg, ng, t0, o0);
    conv_layer<16>(hsm, wsu, colfac, conv_w + 4 * HID * HID * 2, conv_b + 4 * HID, tid, mg, ng, t0, o0);
    conv_layer<32>(hsm, wsu, colfac, conv_w + 5 * HID * HID * 2, conv_b + 5 * HID, tid, mg, ng, t0, o0);
    conv_layer<64>(hsm, wsu, colfac, conv_w + 6 * HID * HID * 2, conv_b + 6 * HID, tid, mg, ng, t0, o0);
    conv_layer<1 >(hsm, wsu, colfac, conv_w + 7 * HID * HID * 2, conv_b + 7 * HID, tid, mg, ng, t0, o0);

    // ---------------- heads: event vectors, switch, top-1, outputs ----------------
    {
        // stage ev_w [16*256] and sw_w [256] into smem
        {
            float4* dst = (float4*)wsu;
            const float4* esrc = (const float4*)ev_w;
            dst[tid]       = esrc[tid];
            dst[tid + 512] = esrc[tid + 512];
            if (tid < 64) ((float4*)(wsu + 4096))[tid] = ((const float4*)sw_w)[tid];
        }
        __syncthreads();
        float* evs = wsu + 4096 + 256;   // [16][128]

        if (tid < TLEN) {
            float a[CTXD + 1];
            #pragma unroll
            for (int c = 0; c < CTXD; c++) a[c] = ev_b[c];
            a[CTXD] = sw_b[0];
            for (int i = 0; i < HID; i++) {
                float hv = hsm[i * TPAD + tid];
                #pragma unroll
                for (int c = 0; c < CTXD; c++) a[c] = fmaf(wsu[c * HID + i], hv, a[c]);
                a[CTXD] = fmaf(wsu[4096 + i], hv, a[CTXD]);
            }
            #pragma unroll
            for (int c = 0; c < CTXD; c++) evs[c * TLEN + tid] = a[c];
            colfac[tid] = fmaxf(a[CTXD], 0.f);   // attn = relu(switch)
        }
        __syncthreads();

        // top-1 over t with lowest-index tie-break (matches jax top_k)
        if (tid < TLEN) {
            float v = colfac[tid]; int idx = tid;
            #pragma unroll
            for (int off = 16; off > 0; off >>= 1) {
                float ov = __shfl_down_sync(0xffffffff, v, off);
                int   oi = __shfl_down_sync(0xffffffff, idx, off);
                if (ov > v || (ov == v && oi < idx)) { v = ov; idx = oi; }
            }
            if ((tid & 31) == 0) { redv[tid >> 5] = v; redi[tid >> 5] = idx; }
        }
        __syncthreads();
        if (tid == 0) {
            float v = redv[0]; int idx = redi[0];
            #pragma unroll
            for (int w = 1; w < 4; w++)
                if (redv[w] > v || (redv[w] == v && redi[w] < idx)) { v = redv[w]; idx = redi[w]; }
            redv[0] = v; redi[0] = idx;
        }
        __syncthreads();

        const int   bi = redi[0];
        const float bv = redv[0];
        // output: [vecs (B*CTX) | scheduling (B*T)]
        if (tid < CTXD) out[(size_t)b * CTXD + tid] = evs[tid * TLEN + bi];
        if (tid < TLEN) out[(size_t)gridDim.x * CTXD + (size_t)b * TLEN + tid] = (tid == bi) ? bv : 0.f;
    }
}

extern "C" void kernel_launch(void* const* d_in, const int* in_sizes, int n_in,
                              void* d_out, int out_size)
{
    const float* x      = (const float*)d_in[0];
    const float* proj_w = (const float*)d_in[1];
    const float* proj_b = (const float*)d_in[2];
    const float* conv_w = (const float*)d_in[3];
    const float* conv_b = (const float*)d_in[4];
    const float* ev_w   = (const float*)d_in[5];
    const float* ev_b   = (const float*)d_in[6];
    const float* sw_w   = (const float*)d_in[7];
    const float* sw_b   = (const float*)d_in[8];
    float* out = (float*)d_out;

    const int B = in_sizes[0] / (INCH * TLEN);   // 256
    const size_t smem = SMEM_FLOATS * sizeof(float);   // ~218 KB
    cudaFuncSetAttribute(Model_26147760898465_kernel,
                         cudaFuncAttributeMaxDynamicSharedMemorySize, (int)smem);
    Model_26147760898465_kernel<<<B, 512, smem>>>(
        x, proj_w, proj_b, conv_w, conv_b, ev_w, ev_b, sw_w, sw_b, out);
}